// round 13
// baseline (speedup 1.0000x reference)
#include <cuda_runtime.h>

// ---------------------------------------------------------------------------
// Problem constants
// ---------------------------------------------------------------------------
constexpr int Bb = 128;   // batch
constexpr int Pp = 49;    // positions
constexpr int Ee = 2048;  // encoder dim
constexpr int Dd = 512;   // decoder dim
constexpr int Aa = 512;   // attention dim

// ---------------------------------------------------------------------------
// Device scratch (allocation-free rule: __device__ globals)
// ---------------------------------------------------------------------------
__device__ float g_att1[Bb * Pp * Aa];            // 12.8 MB  [b*49+p][a]
__device__ float g_att2[Bb * Aa];                 // 256 KB   [b][a]
__device__ float g_u[(size_t)Bb * Aa * Aa];       // 134 MB   [b][k][i]
__device__ float g_attp[Bb * Pp * 4];             // partial att per k-tile

// ---------------------------------------------------------------------------
// f32x2 packed-FMA helpers (Blackwell FFMA2, PTX-only)
// ---------------------------------------------------------------------------
using u64 = unsigned long long;

__device__ __forceinline__ u64 dup2(float x) {
    u64 r; asm("mov.b64 %0, {%1, %1};" : "=l"(r) : "f"(x)); return r;
}
__device__ __forceinline__ u64 ffma2(u64 a, u64 b, u64 c) {
    u64 d; asm("fma.rn.f32x2 %0, %1, %2, %3;" : "=l"(d) : "l"(a), "l"(b), "l"(c)); return d;
}
__device__ __forceinline__ float2 unpk(u64 v) {
    float2 f; asm("mov.b64 {%0, %1}, %2;" : "=f"(f.x), "=f"(f.y) : "l"(v)); return f;
}

// ---------------------------------------------------------------------------
// Kernel 1: att2[b][a] = dot(dh[b,:], Wd[a,:]) + bd[a]
// grid 128 (b), block 256 (each thread does 2 rows of Wd)
// ---------------------------------------------------------------------------
__global__ void __launch_bounds__(256)
k_att2(const float* __restrict__ dh, const float* __restrict__ Wd,
       const float* __restrict__ bd) {
    __shared__ __align__(16) float dhs[Dd];
    const int b = blockIdx.x;
    const int tid = threadIdx.x;
    if (tid < Dd / 4)
        reinterpret_cast<float4*>(dhs)[tid] =
            reinterpret_cast<const float4*>(dh + (size_t)b * Dd)[tid];
    __syncthreads();
#pragma unroll
    for (int s = 0; s < 2; s++) {
        const int a = tid + s * 256;
        const float4* w = reinterpret_cast<const float4*>(Wd + (size_t)a * Dd);
        const float4* x = reinterpret_cast<const float4*>(dhs);
        float acc = 0.f;
#pragma unroll 8
        for (int q = 0; q < Dd / 4; q++) {
            float4 wv = w[q], xv = x[q];
            acc += wv.x * xv.x + wv.y * xv.y + wv.z * xv.z + wv.w * xv.w;
        }
        g_att2[b * Aa + a] = acc + bd[a];
    }
}

// ---------------------------------------------------------------------------
// Shared SGEMM-NT template (compile-time shapes):
//   C[m][n] = sum_k A[m*K+k] * B[n*K+k] (+ bias[n])
// BM=64, BN=128, BK=16, 256 threads, per-thread 4x8 micro-tile via f32x2.
// ASEL: 0 -> A from arg, 1 -> A = g_att2 (device global)
// OSEL: 0 -> C = g_att1,  1 -> C = g_u
// ---------------------------------------------------------------------------
template <int M, int N, int K, int ASEL, int OSEL>
__global__ void __launch_bounds__(256, 2)
sgemm_nt(const float* __restrict__ Ag_, const float* __restrict__ Bg,
         const float* __restrict__ bias) {
    constexpr int BM = 64, BN = 128, BK = 16;
    __shared__ __align__(16) float As[2][BK][BM];
    __shared__ __align__(16) float Bs[2][BK][BN];

    const float* Ag = ASEL ? g_att2 : Ag_;
    float* Cg = OSEL ? g_u : g_att1;

    const int tid = threadIdx.x;
    const int tx = tid & 15, ty = tid >> 4;
    const int m0 = blockIdx.y * BM;
    const int n0 = blockIdx.x * BN;

    // global->smem assignment: float4 per (row, 16-float chunk)
    const int arow = tid >> 2;             // 0..63
    const int ac4  = (tid & 3) * 4;        // 0,4,8,12
    const float* Abase = Ag + (size_t)(m0 + arow) * K + ac4;
    const float* B0    = Bg + (size_t)(n0 + arow) * K + ac4;
    const float* B1    = Bg + (size_t)(n0 + arow + 64) * K + ac4;

    // prologue: stage 0
    {
        float4 ra  = *reinterpret_cast<const float4*>(Abase);
        float4 rb0 = *reinterpret_cast<const float4*>(B0);
        float4 rb1 = *reinterpret_cast<const float4*>(B1);
        As[0][ac4 + 0][arow] = ra.x;  As[0][ac4 + 1][arow] = ra.y;
        As[0][ac4 + 2][arow] = ra.z;  As[0][ac4 + 3][arow] = ra.w;
        Bs[0][ac4 + 0][arow] = rb0.x; Bs[0][ac4 + 1][arow] = rb0.y;
        Bs[0][ac4 + 2][arow] = rb0.z; Bs[0][ac4 + 3][arow] = rb0.w;
        Bs[0][ac4 + 0][arow + 64] = rb1.x; Bs[0][ac4 + 1][arow + 64] = rb1.y;
        Bs[0][ac4 + 2][arow + 64] = rb1.z; Bs[0][ac4 + 3][arow + 64] = rb1.w;
    }
    __syncthreads();

    u64 acc[4][4] = {};
    constexpr int NT = K / BK;
    for (int kt = 0; kt < NT; kt++) {
        const int cur = kt & 1;
        float4 ra, rb0, rb1;
        if (kt + 1 < NT) {
            const int kg = (kt + 1) * BK;
            ra  = *reinterpret_cast<const float4*>(Abase + kg);
            rb0 = *reinterpret_cast<const float4*>(B0 + kg);
            rb1 = *reinterpret_cast<const float4*>(B1 + kg);
        }
#pragma unroll
        for (int kk = 0; kk < BK; kk++) {
            float4 av = *reinterpret_cast<const float4*>(&As[cur][kk][ty * 4]);
            ulonglong2 bq0 = *reinterpret_cast<const ulonglong2*>(&Bs[cur][kk][tx * 8]);
            ulonglong2 bq1 = *reinterpret_cast<const ulonglong2*>(&Bs[cur][kk][tx * 8 + 4]);
            u64 ad0 = dup2(av.x), ad1 = dup2(av.y), ad2 = dup2(av.z), ad3 = dup2(av.w);
            acc[0][0] = ffma2(ad0, bq0.x, acc[0][0]);
            acc[0][1] = ffma2(ad0, bq0.y, acc[0][1]);
            acc[0][2] = ffma2(ad0, bq1.x, acc[0][2]);
            acc[0][3] = ffma2(ad0, bq1.y, acc[0][3]);
            acc[1][0] = ffma2(ad1, bq0.x, acc[1][0]);
            acc[1][1] = ffma2(ad1, bq0.y, acc[1][1]);
            acc[1][2] = ffma2(ad1, bq1.x, acc[1][2]);
            acc[1][3] = ffma2(ad1, bq1.y, acc[1][3]);
            acc[2][0] = ffma2(ad2, bq0.x, acc[2][0]);
            acc[2][1] = ffma2(ad2, bq0.y, acc[2][1]);
            acc[2][2] = ffma2(ad2, bq1.x, acc[2][2]);
            acc[2][3] = ffma2(ad2, bq1.y, acc[2][3]);
            acc[3][0] = ffma2(ad3, bq0.x, acc[3][0]);
            acc[3][1] = ffma2(ad3, bq0.y, acc[3][1]);
            acc[3][2] = ffma2(ad3, bq1.x, acc[3][2]);
            acc[3][3] = ffma2(ad3, bq1.y, acc[3][3]);
        }
        if (kt + 1 < NT) {
            const int nxt = cur ^ 1;
            As[nxt][ac4 + 0][arow] = ra.x;  As[nxt][ac4 + 1][arow] = ra.y;
            As[nxt][ac4 + 2][arow] = ra.z;  As[nxt][ac4 + 3][arow] = ra.w;
            Bs[nxt][ac4 + 0][arow] = rb0.x; Bs[nxt][ac4 + 1][arow] = rb0.y;
            Bs[nxt][ac4 + 2][arow] = rb0.z; Bs[nxt][ac4 + 3][arow] = rb0.w;
            Bs[nxt][ac4 + 0][arow + 64] = rb1.x; Bs[nxt][ac4 + 1][arow + 64] = rb1.y;
            Bs[nxt][ac4 + 2][arow + 64] = rb1.z; Bs[nxt][ac4 + 3][arow + 64] = rb1.w;
            __syncthreads();
        }
    }

    // epilogue
    float bvals[8];
#pragma unroll
    for (int j = 0; j < 8; j++)
        bvals[j] = bias ? bias[n0 + tx * 8 + j] : 0.f;
#pragma unroll
    for (int i = 0; i < 4; i++) {
        const size_t row = (size_t)(m0 + ty * 4 + i) * N + n0 + tx * 8;
        float r[8];
#pragma unroll
        for (int j = 0; j < 4; j++) {
            float2 v = unpk(acc[i][j]);
            r[2 * j]     = v.x + bvals[2 * j];
            r[2 * j + 1] = v.y + bvals[2 * j + 1];
        }
        *reinterpret_cast<float4*>(Cg + row)     = make_float4(r[0], r[1], r[2], r[3]);
        *reinterpret_cast<float4*>(Cg + row + 4) = make_float4(r[4], r[5], r[6], r[7]);
    }
}

// ---------------------------------------------------------------------------
// Kernel 4: per (b, k-tile of 128):
//   bil[p][k] = sum_i att1[b][p][i] * u[b][k][i]   (p padded 49->64)
//   then fused: att_partial[b][p][kt] = sum_k relu(bil + bb[k]) * Wf[k]
// grid (4, 128), block 256
// ---------------------------------------------------------------------------
__global__ void __launch_bounds__(256, 2)
k_bil_att(const float* __restrict__ bb, const float* __restrict__ Wf) {
    constexpr int CI = 16, PP = 64, KT = 128;
    __shared__ __align__(16) float a1s[2][CI][PP];   // 8 KB
    __shared__ __align__(16) float us[2][CI][KT];    // 16 KB
    __shared__ float wf_s[KT], bb_s[KT];

    const int tid = threadIdx.x;
    const int tx = tid & 15, ty = tid >> 4;
    const int ktile = blockIdx.x, b = blockIdx.y;
    const int k0 = ktile * KT;
    if (tid < KT) { wf_s[tid] = Wf[k0 + tid]; bb_s[tid] = bb[k0 + tid]; }

    const float* A1 = g_att1 + (size_t)b * Pp * Aa;
    const float* U  = g_u + (size_t)b * Aa * Aa + (size_t)k0 * Aa;

    const int ar  = tid >> 2;            // 0..63
    const int ac4 = (tid & 3) * 4;
    const bool aval = (ar < Pp);
    const float* A1p = A1 + (size_t)ar * Aa + ac4;
    const float* U0  = U + (size_t)ar * Aa + ac4;
    const float* U1  = U + (size_t)(ar + 64) * Aa + ac4;

    {
        float4 ra  = aval ? *reinterpret_cast<const float4*>(A1p)
                          : make_float4(0.f, 0.f, 0.f, 0.f);
        float4 ru0 = *reinterpret_cast<const float4*>(U0);
        float4 ru1 = *reinterpret_cast<const float4*>(U1);
        a1s[0][ac4 + 0][ar] = ra.x;  a1s[0][ac4 + 1][ar] = ra.y;
        a1s[0][ac4 + 2][ar] = ra.z;  a1s[0][ac4 + 3][ar] = ra.w;
        us[0][ac4 + 0][ar] = ru0.x;  us[0][ac4 + 1][ar] = ru0.y;
        us[0][ac4 + 2][ar] = ru0.z;  us[0][ac4 + 3][ar] = ru0.w;
        us[0][ac4 + 0][ar + 64] = ru1.x; us[0][ac4 + 1][ar + 64] = ru1.y;
        us[0][ac4 + 2][ar + 64] = ru1.z; us[0][ac4 + 3][ar + 64] = ru1.w;
    }
    __syncthreads();

    u64 acc[4][4] = {};
    constexpr int NC = Aa / CI;  // 32
    for (int c = 0; c < NC; c++) {
        const int cur = c & 1;
        float4 ra, ru0, ru1;
        if (c + 1 < NC) {
            const int i0 = (c + 1) * CI;
            ra  = aval ? *reinterpret_cast<const float4*>(A1p + i0)
                       : make_float4(0.f, 0.f, 0.f, 0.f);
            ru0 = *reinterpret_cast<const float4*>(U0 + i0);
            ru1 = *reinterpret_cast<const float4*>(U1 + i0);
        }
#pragma unroll
        for (int ii = 0; ii < CI; ii++) {
            float4 av = *reinterpret_cast<const float4*>(&a1s[cur][ii][ty * 4]);
            ulonglong2 bq0 = *reinterpret_cast<const ulonglong2*>(&us[cur][ii][tx * 8]);
            ulonglong2 bq1 = *reinterpret_cast<const ulonglong2*>(&us[cur][ii][tx * 8 + 4]);
            u64 ad0 = dup2(av.x), ad1 = dup2(av.y), ad2 = dup2(av.z), ad3 = dup2(av.w);
            acc[0][0] = ffma2(ad0, bq0.x, acc[0][0]);
            acc[0][1] = ffma2(ad0, bq0.y, acc[0][1]);
            acc[0][2] = ffma2(ad0, bq1.x, acc[0][2]);
            acc[0][3] = ffma2(ad0, bq1.y, acc[0][3]);
            acc[1][0] = ffma2(ad1, bq0.x, acc[1][0]);
            acc[1][1] = ffma2(ad1, bq0.y, acc[1][1]);
            acc[1][2] = ffma2(ad1, bq1.x, acc[1][2]);
            acc[1][3] = ffma2(ad1, bq1.y, acc[1][3]);
            acc[2][0] = ffma2(ad2, bq0.x, acc[2][0]);
            acc[2][1] = ffma2(ad2, bq0.y, acc[2][1]);
            acc[2][2] = ffma2(ad2, bq1.x, acc[2][2]);
            acc[2][3] = ffma2(ad2, bq1.y, acc[2][3]);
            acc[3][0] = ffma2(ad3, bq0.x, acc[3][0]);
            acc[3][1] = ffma2(ad3, bq0.y, acc[3][1]);
            acc[3][2] = ffma2(ad3, bq1.x, acc[3][2]);
            acc[3][3] = ffma2(ad3, bq1.y, acc[3][3]);
        }
        if (c + 1 < NC) {
            const int nxt = cur ^ 1;
            a1s[nxt][ac4 + 0][ar] = ra.x;  a1s[nxt][ac4 + 1][ar] = ra.y;
            a1s[nxt][ac4 + 2][ar] = ra.z;  a1s[nxt][ac4 + 3][ar] = ra.w;
            us[nxt][ac4 + 0][ar] = ru0.x;  us[nxt][ac4 + 1][ar] = ru0.y;
            us[nxt][ac4 + 2][ar] = ru0.z;  us[nxt][ac4 + 3][ar] = ru0.w;
            us[nxt][ac4 + 0][ar + 64] = ru1.x; us[nxt][ac4 + 1][ar + 64] = ru1.y;
            us[nxt][ac4 + 2][ar + 64] = ru1.z; us[nxt][ac4 + 3][ar + 64] = ru1.w;
            __syncthreads();
        }
    }

    // fused epilogue: relu(bil + bb)*Wf, reduce over this thread's 8 k's
    float s[4] = {0.f, 0.f, 0.f, 0.f};
#pragma unroll
    for (int i = 0; i < 4; i++) {
#pragma unroll
        for (int j = 0; j < 4; j++) {
            float2 v = unpk(acc[i][j]);
            const int kl = tx * 8 + 2 * j;
            s[i] += fmaxf(v.x + bb_s[kl], 0.f) * wf_s[kl];
            s[i] += fmaxf(v.y + bb_s[kl + 1], 0.f) * wf_s[kl + 1];
        }
    }
    __syncthreads();                      // done with a1s -> reuse as reduction buf
    float* red = &a1s[0][0][0];           // [64][17]
#pragma unroll
    for (int i = 0; i < 4; i++) red[(ty * 4 + i) * 17 + tx] = s[i];
    __syncthreads();
    if (tid < Pp) {
        float t = 0.f;
#pragma unroll
        for (int x = 0; x < 16; x++) t += red[tid * 17 + x];
        g_attp[(b * Pp + tid) * 4 + ktile] = t;
    }
}

// ---------------------------------------------------------------------------
// Kernel 5: att -> softmax -> alpha, awe[b][e] = sum_p enc[b][p][e]*alpha[p]
// d_out layout: [awe (128*2048)] then [alpha (128*49)]
// ---------------------------------------------------------------------------
__global__ void __launch_bounds__(256)
k_softmax_awe(const float* __restrict__ enc, const float* __restrict__ bf,
              float* __restrict__ out) {
    __shared__ float al[Pp];
    __shared__ float inv_s;
    const int b = blockIdx.x;
    const int tid = threadIdx.x;

    if (tid < Pp) {
        const float* ap = g_attp + (size_t)(b * Pp + tid) * 4;
        al[tid] = ap[0] + ap[1] + ap[2] + ap[3] + bf[0];
    }
    __syncthreads();
    if (tid == 0) {
        float m = al[0];
        for (int p = 1; p < Pp; p++) m = fmaxf(m, al[p]);
        float ssum = 0.f;
        for (int p = 0; p < Pp; p++) { al[p] = expf(al[p] - m); ssum += al[p]; }
        inv_s = 1.f / ssum;
    }
    __syncthreads();
    if (tid < Pp) {
        al[tid] *= inv_s;
        out[(size_t)Bb * Ee + b * Pp + tid] = al[tid];  // alpha output
    }
    __syncthreads();

    const float* encb = enc + (size_t)b * Pp * Ee;
#pragma unroll
    for (int r = 0; r < Ee / 256; r++) {
        const int e = r * 256 + tid;
        float a0 = 0.f, a1 = 0.f, a2 = 0.f, a3 = 0.f;
        for (int p = 0; p < 48; p += 4) {
            a0 += encb[(size_t)(p + 0) * Ee + e] * al[p + 0];
            a1 += encb[(size_t)(p + 1) * Ee + e] * al[p + 1];
            a2 += encb[(size_t)(p + 2) * Ee + e] * al[p + 2];
            a3 += encb[(size_t)(p + 3) * Ee + e] * al[p + 3];
        }
        a0 += encb[(size_t)48 * Ee + e] * al[48];
        out[(size_t)b * Ee + e] = a0 + a1 + a2 + a3;
    }
}

// ---------------------------------------------------------------------------
// Launch
// ---------------------------------------------------------------------------
extern "C" void kernel_launch(void* const* d_in, const int* in_sizes, int n_in,
                              void* d_out, int out_size) {
    const float* enc = (const float*)d_in[0];  // [128,49,2048]
    const float* dh  = (const float*)d_in[1];  // [128,512]
    const float* We  = (const float*)d_in[2];  // [512,2048]
    const float* be  = (const float*)d_in[3];  // [512]
    const float* Wd  = (const float*)d_in[4];  // [512,512]
    const float* bd  = (const float*)d_in[5];  // [512]
    const float* Wb  = (const float*)d_in[6];  // [512,512,512]
    const float* bb  = (const float*)d_in[7];  // [512]
    const float* Wf  = (const float*)d_in[8];  // [1,512]
    const float* bf  = (const float*)d_in[9];  // [1]
    float* out = (float*)d_out;

    // att2 = dh @ Wd^T + bd
    k_att2<<<128, 256>>>(dh, Wd, bd);

    // att1 = enc @ We^T + be   (M=6272, N=512, K=2048)
    sgemm_nt<6272, 512, 2048, 0, 0><<<dim3(512 / 128, 6272 / 64), 256>>>(enc, We, be);

    // u[b][ki] = att2 @ Wb_flat^T   (M=128, N=262144, K=512)
    sgemm_nt<128, 262144, 512, 1, 1><<<dim3(262144 / 128, 128 / 64), 256>>>(nullptr, Wb, nullptr);

    // bil + relu*Wf partial-att (fused)
    k_bil_att<<<dim3(4, 128), 256>>>(bb, Wf);

    // softmax + attention-weighted encoding
    k_softmax_awe<<<128, 256>>>(enc, bf, out);
}

// round 14
// speedup vs baseline: 1.0018x; 1.0018x over previous
#include <cuda_runtime.h>

// ---------------------------------------------------------------------------
// Problem constants
// ---------------------------------------------------------------------------
constexpr int Bb = 128;   // batch
constexpr int Pp = 49;    // positions
constexpr int Ee = 2048;  // encoder dim
constexpr int Dd = 512;   // decoder dim
constexpr int Aa = 512;   // attention dim

// ---------------------------------------------------------------------------
// Device scratch (allocation-free rule: __device__ globals)
// ---------------------------------------------------------------------------
__device__ float g_att1[Bb * Pp * Aa];            // 12.8 MB  [b*49+p][a]
__device__ float g_att2[Bb * Aa];                 // 256 KB   [b][a]
__device__ float g_u[(size_t)Bb * Aa * Aa];       // 134 MB   [b][k][i]
__device__ float g_attp[Bb * Pp * 4];             // partial att per k-tile

// ---------------------------------------------------------------------------
// f32x2 packed-FMA helpers (Blackwell FFMA2, PTX-only)
// ---------------------------------------------------------------------------
using u64 = unsigned long long;

__device__ __forceinline__ u64 dup2(float x) {
    u64 r; asm("mov.b64 %0, {%1, %1};" : "=l"(r) : "f"(x)); return r;
}
__device__ __forceinline__ u64 ffma2(u64 a, u64 b, u64 c) {
    u64 d; asm("fma.rn.f32x2 %0, %1, %2, %3;" : "=l"(d) : "l"(a), "l"(b), "l"(c)); return d;
}
__device__ __forceinline__ float2 unpk(u64 v) {
    float2 f; asm("mov.b64 {%0, %1}, %2;" : "=f"(f.x), "=f"(f.y) : "l"(v)); return f;
}

// ---------------------------------------------------------------------------
// Kernel 1: att2[b][a] = dot(dh[b,:], Wd[a,:]) + bd[a]
// grid 128 (b), block 256 (each thread does 2 rows of Wd)
// ---------------------------------------------------------------------------
__global__ void __launch_bounds__(256)
k_att2(const float* __restrict__ dh, const float* __restrict__ Wd,
       const float* __restrict__ bd) {
    __shared__ __align__(16) float dhs[Dd];
    const int b = blockIdx.x;
    const int tid = threadIdx.x;
    if (tid < Dd / 4)
        reinterpret_cast<float4*>(dhs)[tid] =
            reinterpret_cast<const float4*>(dh + (size_t)b * Dd)[tid];
    __syncthreads();
#pragma unroll
    for (int s = 0; s < 2; s++) {
        const int a = tid + s * 256;
        const float4* w = reinterpret_cast<const float4*>(Wd + (size_t)a * Dd);
        const float4* x = reinterpret_cast<const float4*>(dhs);
        float acc = 0.f;
#pragma unroll 8
        for (int q = 0; q < Dd / 4; q++) {
            float4 wv = w[q], xv = x[q];
            acc += wv.x * xv.x + wv.y * xv.y + wv.z * xv.z + wv.w * xv.w;
        }
        g_att2[b * Aa + a] = acc + bd[a];
    }
}

// ---------------------------------------------------------------------------
// Shared SGEMM-NT template (compile-time shapes):
//   C[m][n] = sum_k A[m*K+k] * B[n*K+k] (+ bias[n])
// BM=64, BN=128, BK=16, 256 threads, per-thread 4x8 micro-tile via f32x2.
// ASEL: 0 -> A from arg, 1 -> A = g_att2 (device global)
// OSEL: 0 -> C = g_att1,  1 -> C = g_u
// ---------------------------------------------------------------------------
template <int M, int N, int K, int ASEL, int OSEL>
__global__ void __launch_bounds__(256, 2)
sgemm_nt(const float* __restrict__ Ag_, const float* __restrict__ Bg,
         const float* __restrict__ bias) {
    constexpr int BM = 64, BN = 128, BK = 16;
    __shared__ __align__(16) float As[2][BK][BM];
    __shared__ __align__(16) float Bs[2][BK][BN];

    const float* Ag = ASEL ? g_att2 : Ag_;
    float* Cg = OSEL ? g_u : g_att1;

    const int tid = threadIdx.x;
    const int tx = tid & 15, ty = tid >> 4;
    const int m0 = blockIdx.y * BM;
    const int n0 = blockIdx.x * BN;

    // global->smem assignment: float4 per (row, 16-float chunk)
    const int arow = tid >> 2;             // 0..63
    const int ac4  = (tid & 3) * 4;        // 0,4,8,12
    const float* Abase = Ag + (size_t)(m0 + arow) * K + ac4;
    const float* B0    = Bg + (size_t)(n0 + arow) * K + ac4;
    const float* B1    = Bg + (size_t)(n0 + arow + 64) * K + ac4;

    // prologue: stage 0
    {
        float4 ra  = *reinterpret_cast<const float4*>(Abase);
        float4 rb0 = *reinterpret_cast<const float4*>(B0);
        float4 rb1 = *reinterpret_cast<const float4*>(B1);
        As[0][ac4 + 0][arow] = ra.x;  As[0][ac4 + 1][arow] = ra.y;
        As[0][ac4 + 2][arow] = ra.z;  As[0][ac4 + 3][arow] = ra.w;
        Bs[0][ac4 + 0][arow] = rb0.x; Bs[0][ac4 + 1][arow] = rb0.y;
        Bs[0][ac4 + 2][arow] = rb0.z; Bs[0][ac4 + 3][arow] = rb0.w;
        Bs[0][ac4 + 0][arow + 64] = rb1.x; Bs[0][ac4 + 1][arow + 64] = rb1.y;
        Bs[0][ac4 + 2][arow + 64] = rb1.z; Bs[0][ac4 + 3][arow + 64] = rb1.w;
    }
    __syncthreads();

    u64 acc[4][4] = {};
    constexpr int NT = K / BK;
    for (int kt = 0; kt < NT; kt++) {
        const int cur = kt & 1;
        float4 ra, rb0, rb1;
        if (kt + 1 < NT) {
            const int kg = (kt + 1) * BK;
            ra  = *reinterpret_cast<const float4*>(Abase + kg);
            rb0 = *reinterpret_cast<const float4*>(B0 + kg);
            rb1 = *reinterpret_cast<const float4*>(B1 + kg);
        }
#pragma unroll
        for (int kk = 0; kk < BK; kk++) {
            float4 av = *reinterpret_cast<const float4*>(&As[cur][kk][ty * 4]);
            ulonglong2 bq0 = *reinterpret_cast<const ulonglong2*>(&Bs[cur][kk][tx * 8]);
            ulonglong2 bq1 = *reinterpret_cast<const ulonglong2*>(&Bs[cur][kk][tx * 8 + 4]);
            u64 ad0 = dup2(av.x), ad1 = dup2(av.y), ad2 = dup2(av.z), ad3 = dup2(av.w);
            acc[0][0] = ffma2(ad0, bq0.x, acc[0][0]);
            acc[0][1] = ffma2(ad0, bq0.y, acc[0][1]);
            acc[0][2] = ffma2(ad0, bq1.x, acc[0][2]);
            acc[0][3] = ffma2(ad0, bq1.y, acc[0][3]);
            acc[1][0] = ffma2(ad1, bq0.x, acc[1][0]);
            acc[1][1] = ffma2(ad1, bq0.y, acc[1][1]);
            acc[1][2] = ffma2(ad1, bq1.x, acc[1][2]);
            acc[1][3] = ffma2(ad1, bq1.y, acc[1][3]);
            acc[2][0] = ffma2(ad2, bq0.x, acc[2][0]);
            acc[2][1] = ffma2(ad2, bq0.y, acc[2][1]);
            acc[2][2] = ffma2(ad2, bq1.x, acc[2][2]);
            acc[2][3] = ffma2(ad2, bq1.y, acc[2][3]);
            acc[3][0] = ffma2(ad3, bq0.x, acc[3][0]);
            acc[3][1] = ffma2(ad3, bq0.y, acc[3][1]);
            acc[3][2] = ffma2(ad3, bq1.x, acc[3][2]);
            acc[3][3] = ffma2(ad3, bq1.y, acc[3][3]);
        }
        if (kt + 1 < NT) {
            const int nxt = cur ^ 1;
            As[nxt][ac4 + 0][arow] = ra.x;  As[nxt][ac4 + 1][arow] = ra.y;
            As[nxt][ac4 + 2][arow] = ra.z;  As[nxt][ac4 + 3][arow] = ra.w;
            Bs[nxt][ac4 + 0][arow] = rb0.x; Bs[nxt][ac4 + 1][arow] = rb0.y;
            Bs[nxt][ac4 + 2][arow] = rb0.z; Bs[nxt][ac4 + 3][arow] = rb0.w;
            Bs[nxt][ac4 + 0][arow + 64] = rb1.x; Bs[nxt][ac4 + 1][arow + 64] = rb1.y;
            Bs[nxt][ac4 + 2][arow + 64] = rb1.z; Bs[nxt][ac4 + 3][arow + 64] = rb1.w;
            __syncthreads();
        }
    }

    // epilogue
    float bvals[8];
#pragma unroll
    for (int j = 0; j < 8; j++)
        bvals[j] = bias ? bias[n0 + tx * 8 + j] : 0.f;
#pragma unroll
    for (int i = 0; i < 4; i++) {
        const size_t row = (size_t)(m0 + ty * 4 + i) * N + n0 + tx * 8;
        float r[8];
#pragma unroll
        for (int j = 0; j < 4; j++) {
            float2 v = unpk(acc[i][j]);
            r[2 * j]     = v.x + bvals[2 * j];
            r[2 * j + 1] = v.y + bvals[2 * j + 1];
        }
        *reinterpret_cast<float4*>(Cg + row)     = make_float4(r[0], r[1], r[2], r[3]);
        *reinterpret_cast<float4*>(Cg + row + 4) = make_float4(r[4], r[5], r[6], r[7]);
    }
}

// ---------------------------------------------------------------------------
// Kernel 4: per (b, k-tile of 128):
//   bil[p][k] = sum_i att1[b][p][i] * u[b][k][i]   (p padded 49->64)
//   then fused: att_partial[b][p][kt] = sum_k relu(bil + bb[k]) * Wf[k]
// grid (4, 128), block 256
// ---------------------------------------------------------------------------
__global__ void __launch_bounds__(256, 2)
k_bil_att(const float* __restrict__ bb, const float* __restrict__ Wf) {
    constexpr int CI = 16, PP = 64, KT = 128;
    __shared__ __align__(16) float a1s[2][CI][PP];   // 8 KB
    __shared__ __align__(16) float us[2][CI][KT];    // 16 KB
    __shared__ float wf_s[KT], bb_s[KT];

    const int tid = threadIdx.x;
    const int tx = tid & 15, ty = tid >> 4;
    const int ktile = blockIdx.x, b = blockIdx.y;
    const int k0 = ktile * KT;
    if (tid < KT) { wf_s[tid] = Wf[k0 + tid]; bb_s[tid] = bb[k0 + tid]; }

    const float* A1 = g_att1 + (size_t)b * Pp * Aa;
    const float* U  = g_u + (size_t)b * Aa * Aa + (size_t)k0 * Aa;

    const int ar  = tid >> 2;            // 0..63
    const int ac4 = (tid & 3) * 4;
    const bool aval = (ar < Pp);
    const float* A1p = A1 + (size_t)ar * Aa + ac4;
    const float* U0  = U + (size_t)ar * Aa + ac4;
    const float* U1  = U + (size_t)(ar + 64) * Aa + ac4;

    {
        float4 ra  = aval ? *reinterpret_cast<const float4*>(A1p)
                          : make_float4(0.f, 0.f, 0.f, 0.f);
        float4 ru0 = *reinterpret_cast<const float4*>(U0);
        float4 ru1 = *reinterpret_cast<const float4*>(U1);
        a1s[0][ac4 + 0][ar] = ra.x;  a1s[0][ac4 + 1][ar] = ra.y;
        a1s[0][ac4 + 2][ar] = ra.z;  a1s[0][ac4 + 3][ar] = ra.w;
        us[0][ac4 + 0][ar] = ru0.x;  us[0][ac4 + 1][ar] = ru0.y;
        us[0][ac4 + 2][ar] = ru0.z;  us[0][ac4 + 3][ar] = ru0.w;
        us[0][ac4 + 0][ar + 64] = ru1.x; us[0][ac4 + 1][ar + 64] = ru1.y;
        us[0][ac4 + 2][ar + 64] = ru1.z; us[0][ac4 + 3][ar + 64] = ru1.w;
    }
    __syncthreads();

    u64 acc[4][4] = {};
    constexpr int NC = Aa / CI;  // 32
    for (int c = 0; c < NC; c++) {
        const int cur = c & 1;
        float4 ra, ru0, ru1;
        if (c + 1 < NC) {
            const int i0 = (c + 1) * CI;
            ra  = aval ? *reinterpret_cast<const float4*>(A1p + i0)
                       : make_float4(0.f, 0.f, 0.f, 0.f);
            ru0 = *reinterpret_cast<const float4*>(U0 + i0);
            ru1 = *reinterpret_cast<const float4*>(U1 + i0);
        }
#pragma unroll
        for (int ii = 0; ii < CI; ii++) {
            float4 av = *reinterpret_cast<const float4*>(&a1s[cur][ii][ty * 4]);
            ulonglong2 bq0 = *reinterpret_cast<const ulonglong2*>(&us[cur][ii][tx * 8]);
            ulonglong2 bq1 = *reinterpret_cast<const ulonglong2*>(&us[cur][ii][tx * 8 + 4]);
            u64 ad0 = dup2(av.x), ad1 = dup2(av.y), ad2 = dup2(av.z), ad3 = dup2(av.w);
            acc[0][0] = ffma2(ad0, bq0.x, acc[0][0]);
            acc[0][1] = ffma2(ad0, bq0.y, acc[0][1]);
            acc[0][2] = ffma2(ad0, bq1.x, acc[0][2]);
            acc[0][3] = ffma2(ad0, bq1.y, acc[0][3]);
            acc[1][0] = ffma2(ad1, bq0.x, acc[1][0]);
            acc[1][1] = ffma2(ad1, bq0.y, acc[1][1]);
            acc[1][2] = ffma2(ad1, bq1.x, acc[1][2]);
            acc[1][3] = ffma2(ad1, bq1.y, acc[1][3]);
            acc[2][0] = ffma2(ad2, bq0.x, acc[2][0]);
            acc[2][1] = ffma2(ad2, bq0.y, acc[2][1]);
            acc[2][2] = ffma2(ad2, bq1.x, acc[2][2]);
            acc[2][3] = ffma2(ad2, bq1.y, acc[2][3]);
            acc[3][0] = ffma2(ad3, bq0.x, acc[3][0]);
            acc[3][1] = ffma2(ad3, bq0.y, acc[3][1]);
            acc[3][2] = ffma2(ad3, bq1.x, acc[3][2]);
            acc[3][3] = ffma2(ad3, bq1.y, acc[3][3]);
        }
        if (c + 1 < NC) {
            const int nxt = cur ^ 1;
            a1s[nxt][ac4 + 0][ar] = ra.x;  a1s[nxt][ac4 + 1][ar] = ra.y;
            a1s[nxt][ac4 + 2][ar] = ra.z;  a1s[nxt][ac4 + 3][ar] = ra.w;
            us[nxt][ac4 + 0][ar] = ru0.x;  us[nxt][ac4 + 1][ar] = ru0.y;
            us[nxt][ac4 + 2][ar] = ru0.z;  us[nxt][ac4 + 3][ar] = ru0.w;
            us[nxt][ac4 + 0][ar + 64] = ru1.x; us[nxt][ac4 + 1][ar + 64] = ru1.y;
            us[nxt][ac4 + 2][ar + 64] = ru1.z; us[nxt][ac4 + 3][ar + 64] = ru1.w;
            __syncthreads();
        }
    }

    // fused epilogue: relu(bil + bb)*Wf, reduce over this thread's 8 k's
    float s[4] = {0.f, 0.f, 0.f, 0.f};
#pragma unroll
    for (int i = 0; i < 4; i++) {
#pragma unroll
        for (int j = 0; j < 4; j++) {
            float2 v = unpk(acc[i][j]);
            const int kl = tx * 8 + 2 * j;
            s[i] += fmaxf(v.x + bb_s[kl], 0.f) * wf_s[kl];
            s[i] += fmaxf(v.y + bb_s[kl + 1], 0.f) * wf_s[kl + 1];
        }
    }
    __syncthreads();                      // done with a1s -> reuse as reduction buf
    float* red = &a1s[0][0][0];           // [64][17]
#pragma unroll
    for (int i = 0; i < 4; i++) red[(ty * 4 + i) * 17 + tx] = s[i];
    __syncthreads();
    if (tid < Pp) {
        float t = 0.f;
#pragma unroll
        for (int x = 0; x < 16; x++) t += red[tid * 17 + x];
        g_attp[(b * Pp + tid) * 4 + ktile] = t;
    }
}

// ---------------------------------------------------------------------------
// Kernel 5: att -> softmax -> alpha, awe[b][e] = sum_p enc[b][p][e]*alpha[p]
// d_out layout: [awe (128*2048)] then [alpha (128*49)]
// ---------------------------------------------------------------------------
__global__ void __launch_bounds__(256)
k_softmax_awe(const float* __restrict__ enc, const float* __restrict__ bf,
              float* __restrict__ out) {
    __shared__ float al[Pp];
    __shared__ float inv_s;
    const int b = blockIdx.x;
    const int tid = threadIdx.x;

    if (tid < Pp) {
        const float* ap = g_attp + (size_t)(b * Pp + tid) * 4;
        al[tid] = ap[0] + ap[1] + ap[2] + ap[3] + bf[0];
    }
    __syncthreads();
    if (tid == 0) {
        float m = al[0];
        for (int p = 1; p < Pp; p++) m = fmaxf(m, al[p]);
        float ssum = 0.f;
        for (int p = 0; p < Pp; p++) { al[p] = expf(al[p] - m); ssum += al[p]; }
        inv_s = 1.f / ssum;
    }
    __syncthreads();
    if (tid < Pp) {
        al[tid] *= inv_s;
        out[(size_t)Bb * Ee + b * Pp + tid] = al[tid];  // alpha output
    }
    __syncthreads();

    const float* encb = enc + (size_t)b * Pp * Ee;
#pragma unroll
    for (int r = 0; r < Ee / 256; r++) {
        const int e = r * 256 + tid;
        float a0 = 0.f, a1 = 0.f, a2 = 0.f, a3 = 0.f;
        for (int p = 0; p < 48; p += 4) {
            a0 += encb[(size_t)(p + 0) * Ee + e] * al[p + 0];
            a1 += encb[(size_t)(p + 1) * Ee + e] * al[p + 1];
            a2 += encb[(size_t)(p + 2) * Ee + e] * al[p + 2];
            a3 += encb[(size_t)(p + 3) * Ee + e] * al[p + 3];
        }
        a0 += encb[(size_t)48 * Ee + e] * al[48];
        out[(size_t)b * Ee + e] = a0 + a1 + a2 + a3;
    }
}

// ---------------------------------------------------------------------------
// Launch
// ---------------------------------------------------------------------------
extern "C" void kernel_launch(void* const* d_in, const int* in_sizes, int n_in,
                              void* d_out, int out_size) {
    const float* enc = (const float*)d_in[0];  // [128,49,2048]
    const float* dh  = (const float*)d_in[1];  // [128,512]
    const float* We  = (const float*)d_in[2];  // [512,2048]
    const float* be  = (const float*)d_in[3];  // [512]
    const float* Wd  = (const float*)d_in[4];  // [512,512]
    const float* bd  = (const float*)d_in[5];  // [512]
    const float* Wb  = (const float*)d_in[6];  // [512,512,512]
    const float* bb  = (const float*)d_in[7];  // [512]
    const float* Wf  = (const float*)d_in[8];  // [1,512]
    const float* bf  = (const float*)d_in[9];  // [1]
    float* out = (float*)d_out;

    // att2 = dh @ Wd^T + bd
    k_att2<<<128, 256>>>(dh, Wd, bd);

    // att1 = enc @ We^T + be   (M=6272, N=512, K=2048)
    sgemm_nt<6272, 512, 2048, 0, 0><<<dim3(512 / 128, 6272 / 64), 256>>>(enc, We, be);

    // u[b][ki] = att2 @ Wb_flat^T   (M=128, N=262144, K=512)
    sgemm_nt<128, 262144, 512, 1, 1><<<dim3(262144 / 128, 128 / 64), 256>>>(nullptr, Wb, nullptr);

    // bil + relu*Wf partial-att (fused)
    k_bil_att<<<dim3(4, 128), 256>>>(bb, Wf);

    // softmax + attention-weighted encoding
    k_softmax_awe<<<128, 256>>>(enc, bf, out);
}

// round 16
// speedup vs baseline: 2.8917x; 2.8864x over previous
#include <cuda_runtime.h>
#include <cstdint>

// ---------------------------------------------------------------------------
// Problem constants
// ---------------------------------------------------------------------------
constexpr int Bb = 128;   // batch
constexpr int Pp = 49;    // positions
constexpr int Ee = 2048;  // encoder dim
constexpr int Dd = 512;   // decoder dim
constexpr int Aa = 512;   // attention dim

// ---------------------------------------------------------------------------
// Device scratch (allocation-free rule: __device__ globals)
// ---------------------------------------------------------------------------
__device__ float g_att1[Bb * Pp * Aa];            // 12.8 MB  [b*49+p][a]
__device__ float g_att2[Bb * Aa];                 // 256 KB   [b][a]
__device__ float g_u[(size_t)Bb * Aa * Aa];       // 134 MB   [b][k][i]
__device__ float g_attp[Bb * Pp * 4];             // partial att per k-tile

// ---------------------------------------------------------------------------
// f32x2 packed-FMA helpers (for k_bil_att)
// ---------------------------------------------------------------------------
using u64 = unsigned long long;

__device__ __forceinline__ u64 dup2(float x) {
    u64 r; asm("mov.b64 %0, {%1, %1};" : "=l"(r) : "f"(x)); return r;
}
__device__ __forceinline__ u64 ffma2(u64 a, u64 b, u64 c) {
    u64 d; asm("fma.rn.f32x2 %0, %1, %2, %3;" : "=l"(d) : "l"(a), "l"(b), "l"(c)); return d;
}
__device__ __forceinline__ float2 unpk(u64 v) {
    float2 f; asm("mov.b64 {%0, %1}, %2;" : "=f"(f.x), "=f"(f.y) : "l"(v)); return f;
}

// ---------------------------------------------------------------------------
// HMMA helpers (baseline PTX: ldmatrix + mma.sync — no 'a'-target features)
// ---------------------------------------------------------------------------
__device__ __forceinline__ uint32_t smem_u32(const void* p) {
    return (uint32_t)__cvta_generic_to_shared(p);
}

// pack two fp32 -> bf16x2 (x -> lower half, y -> upper half)
__device__ __forceinline__ uint32_t pk2(float x, float y) {
    uint32_t r; asm("cvt.rn.bf16x2.f32 %0, %1, %2;" : "=r"(r) : "f"(y), "f"(x)); return r;
}

__device__ __forceinline__ void ldsm4(uint32_t* r, uint32_t addr) {
    asm volatile("ldmatrix.sync.aligned.m8n8.x4.shared.b16 {%0,%1,%2,%3}, [%4];"
                 : "=r"(r[0]), "=r"(r[1]), "=r"(r[2]), "=r"(r[3]) : "r"(addr));
}

__device__ __forceinline__ void mma_bf16(float* c, const uint32_t* a, const uint32_t* b) {
    asm volatile(
        "mma.sync.aligned.m16n8k16.row.col.f32.bf16.bf16.f32 "
        "{%0,%1,%2,%3}, {%4,%5,%6,%7}, {%8,%9}, {%0,%1,%2,%3};"
        : "+f"(c[0]), "+f"(c[1]), "+f"(c[2]), "+f"(c[3])
        : "r"(a[0]), "r"(a[1]), "r"(a[2]), "r"(a[3]), "r"(b[0]), "r"(b[1]));
}

// load a 128-row x 64-col fp32 tile, split to bf16 hi/lo, store SW128-swizzled
// (each bf16 tile: 128 rows x 128 bytes)
__device__ __forceinline__ void cvt_tile(const float* __restrict__ g, int ld,
                                         char* hi, char* lo, int tid) {
#pragma unroll
    for (int q = 0; q < 8; ++q) {
        const int idx = tid + q * 256;
        const int row = idx >> 4;
        const int c4  = (idx & 15) << 2;
        float4 v = *reinterpret_cast<const float4*>(g + (size_t)row * ld + c4);
        uint32_t h0 = pk2(v.x, v.y);
        uint32_t h1 = pk2(v.z, v.w);
        float fx = __uint_as_float(h0 << 16);
        float fy = __uint_as_float(h0 & 0xFFFF0000u);
        float fz = __uint_as_float(h1 << 16);
        float fw = __uint_as_float(h1 & 0xFFFF0000u);
        uint32_t l0 = pk2(v.x - fx, v.y - fy);
        uint32_t l1 = pk2(v.z - fz, v.w - fw);
        uint32_t off = (uint32_t)(row * 128 + c4 * 2);
        uint32_t sw = off ^ ((off >> 3) & 0x70);
        *reinterpret_cast<uint2*>(hi + sw) = make_uint2(h0, h1);
        *reinterpret_cast<uint2*>(lo + sw) = make_uint2(l0, l1);
    }
}

// ---------------------------------------------------------------------------
// Kernel 1: att2[b][a] = dot(dh[b,:], Wd[a,:]) + bd[a]
// ---------------------------------------------------------------------------
__global__ void __launch_bounds__(256)
k_att2(const float* __restrict__ dh, const float* __restrict__ Wd,
       const float* __restrict__ bd) {
    __shared__ __align__(16) float dhs[Dd];
    const int b = blockIdx.x;
    const int tid = threadIdx.x;
    if (tid < Dd / 4)
        reinterpret_cast<float4*>(dhs)[tid] =
            reinterpret_cast<const float4*>(dh + (size_t)b * Dd)[tid];
    __syncthreads();
#pragma unroll
    for (int s = 0; s < 2; s++) {
        const int a = tid + s * 256;
        const float4* w = reinterpret_cast<const float4*>(Wd + (size_t)a * Dd);
        const float4* x = reinterpret_cast<const float4*>(dhs);
        float acc = 0.f;
#pragma unroll 8
        for (int q = 0; q < Dd / 4; q++) {
            float4 wv = w[q], xv = x[q];
            acc += wv.x * xv.x + wv.y * xv.y + wv.z * xv.z + wv.w * xv.w;
        }
        g_att2[b * Aa + a] = acc + bd[a];
    }
}

// ---------------------------------------------------------------------------
// HMMA split-bf16 GEMM-NT:  C[m][n] = sum_k A[m*K+k]*B[n*K+k] (+bias[n])
// Block tile 128x128, K-chunk 64, 8 warps (warp tile 64x32), 3 products.
// ASEL: 1 -> A = g_att2.  OSEL: 0 -> C = g_att1, 1 -> C = g_u.
// ---------------------------------------------------------------------------
constexpr int SM_TILE = 128 * 128;       // 16 KB per bf16 tile
constexpr int DSMEM   = 4 * SM_TILE;     // Ah, Al, Bh, Bl = 64 KB

template <int Mt, int Nt, int Kt, int ASEL, int OSEL>
__global__ void __launch_bounds__(256)
hmma_gemm(const float* __restrict__ Ag_, const float* __restrict__ Bg,
          const float* __restrict__ bias) {
    extern __shared__ __align__(128) char sm[];
    char* Ah = sm;
    char* Al = sm + SM_TILE;
    char* Bh = sm + 2 * SM_TILE;
    char* Bl = sm + 3 * SM_TILE;

    const float* Ag = ASEL ? g_att2 : Ag_;
    float* Cg = OSEL ? g_u : g_att1;

    const int tid = threadIdx.x;
    const int wid = tid >> 5, lane = tid & 31;
    const int n0 = blockIdx.x * 128;
    const int m0 = blockIdx.y * 128;
    const int wm = (wid >> 2) * 64;       // warp m-offset within block tile
    const int wn = (wid & 3) * 32;        // warp n-offset

    // ldmatrix per-lane address components
    const int a_row  = lane & 15;
    const int a_ksel = (lane >> 4) & 1;                       // 0/1 -> +16B
    const int b_nrow = (lane & 7) + (((lane >> 4) & 1) << 3); // n within 16-row pair
    const int b_ksel = (lane >> 3) & 1;

    float acc[4][4][4] = {};  // [mtile][ntile][c0..c3]

#pragma unroll 1
    for (int it = 0; it < Kt / 64; ++it) {
        if (it) __syncthreads();
        cvt_tile(Ag + (size_t)m0 * Kt + it * 64, Kt, Ah, Al, tid);
        cvt_tile(Bg + (size_t)n0 * Kt + it * 64, Kt, Bh, Bl, tid);
        __syncthreads();

#pragma unroll
        for (int ks = 0; ks < 4; ++ks) {
            uint32_t ah[4][4], alr[4][4], bhr[2][4], blr[2][4];
#pragma unroll
            for (int mt = 0; mt < 4; ++mt) {
                uint32_t off = (uint32_t)((wm + mt * 16 + a_row) * 128
                                          + ks * 32 + a_ksel * 16);
                uint32_t sw = off ^ ((off >> 3) & 0x70);
                ldsm4(ah[mt], smem_u32(Ah + sw));
                ldsm4(alr[mt], smem_u32(Al + sw));
            }
#pragma unroll
            for (int np = 0; np < 2; ++np) {
                uint32_t off = (uint32_t)((wn + np * 16 + b_nrow) * 128
                                          + ks * 32 + b_ksel * 16);
                uint32_t sw = off ^ ((off >> 3) & 0x70);
                ldsm4(bhr[np], smem_u32(Bh + sw));
                ldsm4(blr[np], smem_u32(Bl + sw));
            }
#pragma unroll
            for (int mt = 0; mt < 4; ++mt) {
#pragma unroll
                for (int nt = 0; nt < 4; ++nt) {
                    const uint32_t* bph = &bhr[nt >> 1][(nt & 1) * 2];
                    const uint32_t* bpl = &blr[nt >> 1][(nt & 1) * 2];
                    mma_bf16(acc[mt][nt], ah[mt], bph);   // hi*hi
                    mma_bf16(acc[mt][nt], ah[mt], bpl);   // hi*lo
                    mma_bf16(acc[mt][nt], alr[mt], bph);  // lo*hi
                }
            }
        }
    }

    // epilogue: c0,c1 -> (m, n), (m, n+1); c2,c3 -> (m+8, n), (m+8, n+1)
    const int qr = lane >> 2;
    const int qc = (lane & 3) * 2;
#pragma unroll
    for (int mt = 0; mt < 4; ++mt) {
#pragma unroll
        for (int nt = 0; nt < 4; ++nt) {
            const int n = n0 + wn + nt * 8 + qc;
            float b0 = 0.f, b1 = 0.f;
            if (bias != nullptr) { b0 = bias[n]; b1 = bias[n + 1]; }
            const int m = m0 + wm + mt * 16 + qr;
            *reinterpret_cast<float2*>(Cg + (size_t)m * Nt + n) =
                make_float2(acc[mt][nt][0] + b0, acc[mt][nt][1] + b1);
            *reinterpret_cast<float2*>(Cg + (size_t)(m + 8) * Nt + n) =
                make_float2(acc[mt][nt][2] + b0, acc[mt][nt][3] + b1);
        }
    }
}

// ---------------------------------------------------------------------------
// Kernel 4: per (b, k-tile of 128):
//   bil[p][k] = sum_i att1[b][p][i] * u[b][k][i]   (p padded 49->64)
//   then fused: att_partial[b][p][kt] = sum_k relu(bil + bb[k]) * Wf[k]
// ---------------------------------------------------------------------------
__global__ void __launch_bounds__(256, 2)
k_bil_att(const float* __restrict__ bb, const float* __restrict__ Wf) {
    constexpr int CI = 16, PP = 64, KT = 128;
    __shared__ __align__(16) float a1s[2][CI][PP];
    __shared__ __align__(16) float us[2][CI][KT];
    __shared__ float wf_s[KT], bb_s[KT];

    const int tid = threadIdx.x;
    const int tx = tid & 15, ty = tid >> 4;
    const int ktile = blockIdx.x, b = blockIdx.y;
    const int k0 = ktile * KT;
    if (tid < KT) { wf_s[tid] = Wf[k0 + tid]; bb_s[tid] = bb[k0 + tid]; }

    const float* A1 = g_att1 + (size_t)b * Pp * Aa;
    const float* U  = g_u + (size_t)b * Aa * Aa + (size_t)k0 * Aa;

    const int ar  = tid >> 2;
    const int ac4 = (tid & 3) * 4;
    const bool aval = (ar < Pp);
    const float* A1p = A1 + (size_t)ar * Aa + ac4;
    const float* U0  = U + (size_t)ar * Aa + ac4;
    const float* U1  = U + (size_t)(ar + 64) * Aa + ac4;

    {
        float4 ra  = aval ? *reinterpret_cast<const float4*>(A1p)
                          : make_float4(0.f, 0.f, 0.f, 0.f);
        float4 ru0 = *reinterpret_cast<const float4*>(U0);
        float4 ru1 = *reinterpret_cast<const float4*>(U1);
        a1s[0][ac4 + 0][ar] = ra.x;  a1s[0][ac4 + 1][ar] = ra.y;
        a1s[0][ac4 + 2][ar] = ra.z;  a1s[0][ac4 + 3][ar] = ra.w;
        us[0][ac4 + 0][ar] = ru0.x;  us[0][ac4 + 1][ar] = ru0.y;
        us[0][ac4 + 2][ar] = ru0.z;  us[0][ac4 + 3][ar] = ru0.w;
        us[0][ac4 + 0][ar + 64] = ru1.x; us[0][ac4 + 1][ar + 64] = ru1.y;
        us[0][ac4 + 2][ar + 64] = ru1.z; us[0][ac4 + 3][ar + 64] = ru1.w;
    }
    __syncthreads();

    u64 acc[4][4] = {};
    constexpr int NC = Aa / CI;
    for (int c = 0; c < NC; c++) {
        const int cur = c & 1;
        float4 ra, ru0, ru1;
        if (c + 1 < NC) {
            const int i0 = (c + 1) * CI;
            ra  = aval ? *reinterpret_cast<const float4*>(A1p + i0)
                       : make_float4(0.f, 0.f, 0.f, 0.f);
            ru0 = *reinterpret_cast<const float4*>(U0 + i0);
            ru1 = *reinterpret_cast<const float4*>(U1 + i0);
        }
#pragma unroll
        for (int ii = 0; ii < CI; ii++) {
            float4 av = *reinterpret_cast<const float4*>(&a1s[cur][ii][ty * 4]);
            ulonglong2 bq0 = *reinterpret_cast<const ulonglong2*>(&us[cur][ii][tx * 8]);
            ulonglong2 bq1 = *reinterpret_cast<const ulonglong2*>(&us[cur][ii][tx * 8 + 4]);
            u64 ad0 = dup2(av.x), ad1 = dup2(av.y), ad2 = dup2(av.z), ad3 = dup2(av.w);
            acc[0][0] = ffma2(ad0, bq0.x, acc[0][0]);
            acc[0][1] = ffma2(ad0, bq0.y, acc[0][1]);
            acc[0][2] = ffma2(ad0, bq1.x, acc[0][2]);
            acc[0][3] = ffma2(ad0, bq1.y, acc[0][3]);
            acc[1][0] = ffma2(ad1, bq0.x, acc[1][0]);
            acc[1][1] = ffma2(ad1, bq0.y, acc[1][1]);
            acc[1][2] = ffma2(ad1, bq1.x, acc[1][2]);
            acc[1][3] = ffma2(ad1, bq1.y, acc[1][3]);
            acc[2][0] = ffma2(ad2, bq0.x, acc[2][0]);
            acc[2][1] = ffma2(ad2, bq0.y, acc[2][1]);
            acc[2][2] = ffma2(ad2, bq1.x, acc[2][2]);
            acc[2][3] = ffma2(ad2, bq1.y, acc[2][3]);
            acc[3][0] = ffma2(ad3, bq0.x, acc[3][0]);
            acc[3][1] = ffma2(ad3, bq0.y, acc[3][1]);
            acc[3][2] = ffma2(ad3, bq1.x, acc[3][2]);
            acc[3][3] = ffma2(ad3, bq1.y, acc[3][3]);
        }
        if (c + 1 < NC) {
            const int nxt = cur ^ 1;
            a1s[nxt][ac4 + 0][ar] = ra.x;  a1s[nxt][ac4 + 1][ar] = ra.y;
            a1s[nxt][ac4 + 2][ar] = ra.z;  a1s[nxt][ac4 + 3][ar] = ra.w;
            us[nxt][ac4 + 0][ar] = ru0.x;  us[nxt][ac4 + 1][ar] = ru0.y;
            us[nxt][ac4 + 2][ar] = ru0.z;  us[nxt][ac4 + 3][ar] = ru0.w;
            us[nxt][ac4 + 0][ar + 64] = ru1.x; us[nxt][ac4 + 1][ar + 64] = ru1.y;
            us[nxt][ac4 + 2][ar + 64] = ru1.z; us[nxt][ac4 + 3][ar + 64] = ru1.w;
            __syncthreads();
        }
    }

    float s[4] = {0.f, 0.f, 0.f, 0.f};
#pragma unroll
    for (int i = 0; i < 4; i++) {
#pragma unroll
        for (int j = 0; j < 4; j++) {
            float2 v = unpk(acc[i][j]);
            const int kl = tx * 8 + 2 * j;
            s[i] += fmaxf(v.x + bb_s[kl], 0.f) * wf_s[kl];
            s[i] += fmaxf(v.y + bb_s[kl + 1], 0.f) * wf_s[kl + 1];
        }
    }
    __syncthreads();
    float* red = &a1s[0][0][0];
#pragma unroll
    for (int i = 0; i < 4; i++) red[(ty * 4 + i) * 17 + tx] = s[i];
    __syncthreads();
    if (tid < Pp) {
        float t = 0.f;
#pragma unroll
        for (int x = 0; x < 16; x++) t += red[tid * 17 + x];
        g_attp[(b * Pp + tid) * 4 + ktile] = t;
    }
}

// ---------------------------------------------------------------------------
// Kernel 5: softmax + attention-weighted encoding
// ---------------------------------------------------------------------------
__global__ void __launch_bounds__(256)
k_softmax_awe(const float* __restrict__ enc, const float* __restrict__ bf,
              float* __restrict__ out) {
    __shared__ float al[Pp];
    __shared__ float inv_s;
    const int b = blockIdx.x;
    const int tid = threadIdx.x;

    if (tid < Pp) {
        const float* ap = g_attp + (size_t)(b * Pp + tid) * 4;
        al[tid] = ap[0] + ap[1] + ap[2] + ap[3] + bf[0];
    }
    __syncthreads();
    if (tid == 0) {
        float m = al[0];
        for (int p = 1; p < Pp; p++) m = fmaxf(m, al[p]);
        float ssum = 0.f;
        for (int p = 0; p < Pp; p++) { al[p] = expf(al[p] - m); ssum += al[p]; }
        inv_s = 1.f / ssum;
    }
    __syncthreads();
    if (tid < Pp) {
        al[tid] *= inv_s;
        out[(size_t)Bb * Ee + b * Pp + tid] = al[tid];
    }
    __syncthreads();

    const float* encb = enc + (size_t)b * Pp * Ee;
#pragma unroll
    for (int r = 0; r < Ee / 256; r++) {
        const int e = r * 256 + tid;
        float a0 = 0.f, a1 = 0.f, a2 = 0.f, a3 = 0.f;
        for (int p = 0; p < 48; p += 4) {
            a0 += encb[(size_t)(p + 0) * Ee + e] * al[p + 0];
            a1 += encb[(size_t)(p + 1) * Ee + e] * al[p + 1];
            a2 += encb[(size_t)(p + 2) * Ee + e] * al[p + 2];
            a3 += encb[(size_t)(p + 3) * Ee + e] * al[p + 3];
        }
        a0 += encb[(size_t)48 * Ee + e] * al[48];
        out[(size_t)b * Ee + e] = a0 + a1 + a2 + a3;
    }
}

// ---------------------------------------------------------------------------
// Launch
// ---------------------------------------------------------------------------
extern "C" void kernel_launch(void* const* d_in, const int* in_sizes, int n_in,
                              void* d_out, int out_size) {
    const float* enc = (const float*)d_in[0];  // [128,49,2048]
    const float* dh  = (const float*)d_in[1];  // [128,512]
    const float* We  = (const float*)d_in[2];  // [512,2048]
    const float* be  = (const float*)d_in[3];  // [512]
    const float* Wd  = (const float*)d_in[4];  // [512,512]
    const float* bd  = (const float*)d_in[5];  // [512]
    const float* Wb  = (const float*)d_in[6];  // [512,512,512]
    const float* bb  = (const float*)d_in[7];  // [512]
    const float* Wf  = (const float*)d_in[8];  // [1,512]
    const float* bf  = (const float*)d_in[9];  // [1]
    float* out = (float*)d_out;

    cudaFuncSetAttribute((const void*)&hmma_gemm<6272, 512, 2048, 0, 0>,
                         cudaFuncAttributeMaxDynamicSharedMemorySize, DSMEM);
    cudaFuncSetAttribute((const void*)&hmma_gemm<128, 262144, 512, 1, 1>,
                         cudaFuncAttributeMaxDynamicSharedMemorySize, DSMEM);

    // att2 = dh @ Wd^T + bd
    k_att2<<<128, 256>>>(dh, Wd, bd);

    // att1 = enc @ We^T + be   (M=6272, N=512, K=2048) — HMMA split-bf16
    hmma_gemm<6272, 512, 2048, 0, 0>
        <<<dim3(512 / 128, 6272 / 128), 256, DSMEM>>>(enc, We, be);

    // u[b][ki] = att2 @ Wb_flat^T   (M=128, N=262144, K=512) — HMMA split-bf16
    hmma_gemm<128, 262144, 512, 1, 1>
        <<<dim3(262144 / 128, 1), 256, DSMEM>>>(nullptr, Wb, nullptr);

    // bil + relu*Wf partial-att (fused, fp32)
    k_bil_att<<<dim3(4, 128), 256>>>(bb, Wf);

    // softmax + attention-weighted encoding
    k_softmax_awe<<<128, 256>>>(enc, bf, out);
}

// round 17
// speedup vs baseline: 3.4999x; 1.2103x over previous
#include <cuda_runtime.h>
#include <cstdint>

// ---------------------------------------------------------------------------
// Problem constants
// ---------------------------------------------------------------------------
constexpr int Bb = 128;   // batch
constexpr int Pp = 49;    // positions
constexpr int Ee = 2048;  // encoder dim
constexpr int Dd = 512;   // decoder dim
constexpr int Aa = 512;   // attention dim

// ---------------------------------------------------------------------------
// Device scratch (allocation-free rule: __device__ globals)
// Split-bf16 planes, packed as uint32 = two adjacent-n bf16 values.
// att1 planes padded by 16 rows so k_bil_att can read 64-row tiles at b=127.
// ---------------------------------------------------------------------------
constexpr int A1_ROWS = Bb * Pp + 16;               // 6288
__device__ uint32_t g_a1h[A1_ROWS * Aa / 2];        // 6.4 MB hi plane
__device__ uint32_t g_a1l[A1_ROWS * Aa / 2];        // 6.4 MB lo plane
__device__ uint32_t g_uh[(size_t)Bb * Aa * Aa / 2]; // 67 MB hi plane
__device__ uint32_t g_ul[(size_t)Bb * Aa * Aa / 2]; // 67 MB lo plane
__device__ float g_att2[Bb * Aa];                   // 256 KB [b][a]
__device__ float g_attp[Bb * Pp * 4];               // partial att per k-tile

// ---------------------------------------------------------------------------
// HMMA helpers (baseline PTX: ldmatrix + mma.sync)
// ---------------------------------------------------------------------------
__device__ __forceinline__ uint32_t smem_u32(const void* p) {
    return (uint32_t)__cvta_generic_to_shared(p);
}

// pack two fp32 -> bf16x2 (x -> lower half, y -> upper half)
__device__ __forceinline__ uint32_t pk2(float x, float y) {
    uint32_t r; asm("cvt.rn.bf16x2.f32 %0, %1, %2;" : "=r"(r) : "f"(y), "f"(x)); return r;
}

__device__ __forceinline__ void ldsm4(uint32_t* r, uint32_t addr) {
    asm volatile("ldmatrix.sync.aligned.m8n8.x4.shared.b16 {%0,%1,%2,%3}, [%4];"
                 : "=r"(r[0]), "=r"(r[1]), "=r"(r[2]), "=r"(r[3]) : "r"(addr));
}

__device__ __forceinline__ void mma_bf16(float* c, const uint32_t* a, const uint32_t* b) {
    asm volatile(
        "mma.sync.aligned.m16n8k16.row.col.f32.bf16.bf16.f32 "
        "{%0,%1,%2,%3}, {%4,%5,%6,%7}, {%8,%9}, {%0,%1,%2,%3};"
        : "+f"(c[0]), "+f"(c[1]), "+f"(c[2]), "+f"(c[3])
        : "r"(a[0]), "r"(a[1]), "r"(a[2]), "r"(a[3]), "r"(b[0]), "r"(b[1]));
}

// load a 128-row x 64-col fp32 tile, split to bf16 hi/lo, store SW128-swizzled
__device__ __forceinline__ void cvt_tile(const float* __restrict__ g, int ld,
                                         char* hi, char* lo, int tid) {
#pragma unroll
    for (int q = 0; q < 8; ++q) {
        const int idx = tid + q * 256;
        const int row = idx >> 4;
        const int c4  = (idx & 15) << 2;
        float4 v = *reinterpret_cast<const float4*>(g + (size_t)row * ld + c4);
        uint32_t h0 = pk2(v.x, v.y);
        uint32_t h1 = pk2(v.z, v.w);
        float fx = __uint_as_float(h0 << 16);
        float fy = __uint_as_float(h0 & 0xFFFF0000u);
        float fz = __uint_as_float(h1 << 16);
        float fw = __uint_as_float(h1 & 0xFFFF0000u);
        uint32_t l0 = pk2(v.x - fx, v.y - fy);
        uint32_t l1 = pk2(v.z - fz, v.w - fw);
        uint32_t off = (uint32_t)(row * 128 + c4 * 2);
        uint32_t sw = off ^ ((off >> 3) & 0x70);
        *reinterpret_cast<uint2*>(hi + sw) = make_uint2(h0, h1);
        *reinterpret_cast<uint2*>(lo + sw) = make_uint2(l0, l1);
    }
}

// ---------------------------------------------------------------------------
// Kernel 1: att2[b][a] = dot(dh[b,:], Wd[a,:]) + bd[a]
// ---------------------------------------------------------------------------
__global__ void __launch_bounds__(256)
k_att2(const float* __restrict__ dh, const float* __restrict__ Wd,
       const float* __restrict__ bd) {
    __shared__ __align__(16) float dhs[Dd];
    const int b = blockIdx.x;
    const int tid = threadIdx.x;
    if (tid < Dd / 4)
        reinterpret_cast<float4*>(dhs)[tid] =
            reinterpret_cast<const float4*>(dh + (size_t)b * Dd)[tid];
    __syncthreads();
#pragma unroll
    for (int s = 0; s < 2; s++) {
        const int a = tid + s * 256;
        const float4* w = reinterpret_cast<const float4*>(Wd + (size_t)a * Dd);
        const float4* x = reinterpret_cast<const float4*>(dhs);
        float acc = 0.f;
#pragma unroll 8
        for (int q = 0; q < Dd / 4; q++) {
            float4 wv = w[q], xv = x[q];
            acc += wv.x * xv.x + wv.y * xv.y + wv.z * xv.z + wv.w * xv.w;
        }
        g_att2[b * Aa + a] = acc + bd[a];
    }
}

// ---------------------------------------------------------------------------
// HMMA split-bf16 GEMM-NT:  C[m][n] = sum_k A[m*K+k]*B[n*K+k] (+bias[n])
// Block tile 128x128, K-chunk 64, 8 warps (warp tile 64x32), 3 products.
// Output: split-bf16 planes (hi/lo), packed 2 per uint32.
// ASEL: 1 -> A = g_att2.  OSEL: 0 -> att1 planes, 1 -> u planes.
// ---------------------------------------------------------------------------
constexpr int SM_TILE = 128 * 128;       // 16 KB per bf16 tile
constexpr int DSMEM   = 4 * SM_TILE;     // Ah, Al, Bh, Bl = 64 KB

template <int Mt, int Nt, int Kt, int ASEL, int OSEL>
__global__ void __launch_bounds__(256)
hmma_gemm(const float* __restrict__ Ag_, const float* __restrict__ Bg,
          const float* __restrict__ bias) {
    extern __shared__ __align__(128) char sm[];
    char* Ah = sm;
    char* Al = sm + SM_TILE;
    char* Bh = sm + 2 * SM_TILE;
    char* Bl = sm + 3 * SM_TILE;

    const float* Ag = ASEL ? g_att2 : Ag_;
    uint32_t* Hp = OSEL ? g_uh : g_a1h;
    uint32_t* Lp = OSEL ? g_ul : g_a1l;

    const int tid = threadIdx.x;
    const int wid = tid >> 5, lane = tid & 31;
    const int n0 = blockIdx.x * 128;
    const int m0 = blockIdx.y * 128;
    const int wm = (wid >> 2) * 64;       // warp m-offset within block tile
    const int wn = (wid & 3) * 32;        // warp n-offset

    const int a_row  = lane & 15;
    const int a_ksel = (lane >> 4) & 1;
    const int b_nrow = (lane & 7) + (((lane >> 4) & 1) << 3);
    const int b_ksel = (lane >> 3) & 1;

    float acc[4][4][4] = {};  // [mtile][ntile][c0..c3]

#pragma unroll 1
    for (int it = 0; it < Kt / 64; ++it) {
        if (it) __syncthreads();
        cvt_tile(Ag + (size_t)m0 * Kt + it * 64, Kt, Ah, Al, tid);
        cvt_tile(Bg + (size_t)n0 * Kt + it * 64, Kt, Bh, Bl, tid);
        __syncthreads();

#pragma unroll
        for (int ks = 0; ks < 4; ++ks) {
            uint32_t ah[4][4], alr[4][4], bhr[2][4], blr[2][4];
#pragma unroll
            for (int mt = 0; mt < 4; ++mt) {
                uint32_t off = (uint32_t)((wm + mt * 16 + a_row) * 128
                                          + ks * 32 + a_ksel * 16);
                uint32_t sw = off ^ ((off >> 3) & 0x70);
                ldsm4(ah[mt], smem_u32(Ah + sw));
                ldsm4(alr[mt], smem_u32(Al + sw));
            }
#pragma unroll
            for (int np = 0; np < 2; ++np) {
                uint32_t off = (uint32_t)((wn + np * 16 + b_nrow) * 128
                                          + ks * 32 + b_ksel * 16);
                uint32_t sw = off ^ ((off >> 3) & 0x70);
                ldsm4(bhr[np], smem_u32(Bh + sw));
                ldsm4(blr[np], smem_u32(Bl + sw));
            }
#pragma unroll
            for (int mt = 0; mt < 4; ++mt) {
#pragma unroll
                for (int nt = 0; nt < 4; ++nt) {
                    const uint32_t* bph = &bhr[nt >> 1][(nt & 1) * 2];
                    const uint32_t* bpl = &blr[nt >> 1][(nt & 1) * 2];
                    mma_bf16(acc[mt][nt], ah[mt], bph);   // hi*hi
                    mma_bf16(acc[mt][nt], ah[mt], bpl);   // hi*lo
                    mma_bf16(acc[mt][nt], alr[mt], bph);  // lo*hi
                }
            }
        }
    }

    // epilogue: bias add, split to bf16 hi/lo, store packed planes
    const int qr = lane >> 2;
    const int qc = (lane & 3) * 2;
#pragma unroll
    for (int mt = 0; mt < 4; ++mt) {
#pragma unroll
        for (int nt = 0; nt < 4; ++nt) {
            const int n = n0 + wn + nt * 8 + qc;
            float b0 = 0.f, b1 = 0.f;
            if (bias != nullptr) { b0 = bias[n]; b1 = bias[n + 1]; }
            const int m = m0 + wm + mt * 16 + qr;
            float v0 = acc[mt][nt][0] + b0, v1 = acc[mt][nt][1] + b1;
            float v2 = acc[mt][nt][2] + b0, v3 = acc[mt][nt][3] + b1;
            uint32_t hA = pk2(v0, v1);
            uint32_t lA = pk2(v0 - __uint_as_float(hA << 16),
                              v1 - __uint_as_float(hA & 0xFFFF0000u));
            uint32_t hB = pk2(v2, v3);
            uint32_t lB = pk2(v2 - __uint_as_float(hB << 16),
                              v3 - __uint_as_float(hB & 0xFFFF0000u));
            const size_t i0 = (size_t)m * (Nt / 2) + (n >> 1);
            const size_t i1 = (size_t)(m + 8) * (Nt / 2) + (n >> 1);
            Hp[i0] = hA; Lp[i0] = lA;
            Hp[i1] = hB; Lp[i1] = lB;
        }
    }
}

// ---------------------------------------------------------------------------
// Kernel 4 (HMMA): per (b, k-tile of 128):
//   bil[p][k] = sum_i att1[b][p][i] * u[b][k][i]   (p padded 49->64)
//   fused: att_partial[b][p][ktile] = sum_k relu(bil + bb[k]) * Wf[k]
// A = att1 split planes (64x512), B = u split planes (128x512), 8 i-chunks.
// 8 warps, warp tile 32x32.
// ---------------------------------------------------------------------------
constexpr int BIL_SMEM = 64 * 128 * 2 + 128 * 128 * 2;  // Ah+Al+Bh+Bl = 48 KB

__global__ void __launch_bounds__(256)
k_bil_att(const float* __restrict__ bb, const float* __restrict__ Wf) {
    extern __shared__ __align__(128) char sm[];
    char* Ah = sm;                    // 64 rows x 128 B
    char* Al = sm + 8192;
    char* Bh = sm + 16384;            // 128 rows x 128 B
    char* Bl = sm + 32768;
    __shared__ float wf_s[128], bb_s[128];

    const int tid = threadIdx.x;
    const int wid = tid >> 5, lane = tid & 31;
    const int ktile = blockIdx.x, b = blockIdx.y;
    const int k0 = ktile * 128;
    if (tid < 128) { wf_s[tid] = Wf[k0 + tid]; bb_s[tid] = bb[k0 + tid]; }

    const char* a1h = (const char*)g_a1h + (size_t)(b * Pp) * 1024;  // row=1024B
    const char* a1l = (const char*)g_a1l + (size_t)(b * Pp) * 1024;
    const char* uh  = (const char*)g_uh + (size_t)b * 524288 + (size_t)k0 * 1024;
    const char* ul  = (const char*)g_ul + (size_t)b * 524288 + (size_t)k0 * 1024;

    const int wm = (wid >> 2) * 32;   // warp p-offset
    const int wn = (wid & 3) * 32;    // warp k-offset
    const int a_row  = lane & 15;
    const int a_ksel = (lane >> 4) & 1;
    const int b_nrow = (lane & 7) + (((lane >> 4) & 1) << 3);
    const int b_ksel = (lane >> 3) & 1;

    float acc[2][4][4] = {};  // [mtile][ntile][c0..c3]

#pragma unroll 1
    for (int ch = 0; ch < 8; ++ch) {
        if (ch) __syncthreads();
        // load A planes: 64 rows x 128B = 512 uint4
#pragma unroll
        for (int q = 0; q < 2; ++q) {
            const int idx = tid + q * 256;
            const int r = idx >> 3;
            const int c = (idx & 7) * 16;
            const size_t src = (size_t)r * 1024 + ch * 128 + c;
            uint32_t off = (uint32_t)(r * 128 + c);
            uint32_t sw = off ^ ((off >> 3) & 0x70);
            *reinterpret_cast<uint4*>(Ah + sw) =
                *reinterpret_cast<const uint4*>(a1h + src);
            *reinterpret_cast<uint4*>(Al + sw) =
                *reinterpret_cast<const uint4*>(a1l + src);
        }
        // load B planes: 128 rows x 128B = 1024 uint4
#pragma unroll
        for (int q = 0; q < 4; ++q) {
            const int idx = tid + q * 256;
            const int r = idx >> 3;
            const int c = (idx & 7) * 16;
            const size_t src = (size_t)r * 1024 + ch * 128 + c;
            uint32_t off = (uint32_t)(r * 128 + c);
            uint32_t sw = off ^ ((off >> 3) & 0x70);
            *reinterpret_cast<uint4*>(Bh + sw) =
                *reinterpret_cast<const uint4*>(uh + src);
            *reinterpret_cast<uint4*>(Bl + sw) =
                *reinterpret_cast<const uint4*>(ul + src);
        }
        __syncthreads();

#pragma unroll
        for (int ks = 0; ks < 4; ++ks) {
            uint32_t ah[2][4], alr[2][4], bhr[2][4], blr[2][4];
#pragma unroll
            for (int mt = 0; mt < 2; ++mt) {
                uint32_t off = (uint32_t)((wm + mt * 16 + a_row) * 128
                                          + ks * 32 + a_ksel * 16);
                uint32_t sw = off ^ ((off >> 3) & 0x70);
                ldsm4(ah[mt], smem_u32(Ah + sw));
                ldsm4(alr[mt], smem_u32(Al + sw));
            }
#pragma unroll
            for (int np = 0; np < 2; ++np) {
                uint32_t off = (uint32_t)((wn + np * 16 + b_nrow) * 128
                                          + ks * 32 + b_ksel * 16);
                uint32_t sw = off ^ ((off >> 3) & 0x70);
                ldsm4(bhr[np], smem_u32(Bh + sw));
                ldsm4(blr[np], smem_u32(Bl + sw));
            }
#pragma unroll
            for (int mt = 0; mt < 2; ++mt) {
#pragma unroll
                for (int nt = 0; nt < 4; ++nt) {
                    const uint32_t* bph = &bhr[nt >> 1][(nt & 1) * 2];
                    const uint32_t* bpl = &blr[nt >> 1][(nt & 1) * 2];
                    mma_bf16(acc[mt][nt], ah[mt], bph);
                    mma_bf16(acc[mt][nt], ah[mt], bpl);
                    mma_bf16(acc[mt][nt], alr[mt], bph);
                }
            }
        }
    }

    // fused epilogue: relu(bil + bb)*Wf, per-lane partial over its 8 k's
    const int qr = lane >> 2;
    const int qc = (lane & 3) * 2;
    float s[4] = {0.f, 0.f, 0.f, 0.f};  // [mt*2 + half]
#pragma unroll
    for (int mt = 0; mt < 2; ++mt) {
#pragma unroll
        for (int nt = 0; nt < 4; ++nt) {
            const int kl = wn + nt * 8 + qc;
            const float* c = acc[mt][nt];
            s[mt * 2 + 0] += fmaxf(c[0] + bb_s[kl], 0.f) * wf_s[kl]
                           + fmaxf(c[1] + bb_s[kl + 1], 0.f) * wf_s[kl + 1];
            s[mt * 2 + 1] += fmaxf(c[2] + bb_s[kl], 0.f) * wf_s[kl]
                           + fmaxf(c[3] + bb_s[kl + 1], 0.f) * wf_s[kl + 1];
        }
    }
    __syncthreads();                        // done with tiles -> reuse as red buf
    float* red = reinterpret_cast<float*>(Ah);  // [64][17]
    const int slot = (wid & 3) * 4 + (lane & 3);
#pragma unroll
    for (int mt = 0; mt < 2; ++mt)
#pragma unroll
        for (int half = 0; half < 2; ++half) {
            const int p = wm + mt * 16 + half * 8 + qr;
            red[p * 17 + slot] = s[mt * 2 + half];
        }
    __syncthreads();
    if (tid < Pp) {
        float t = 0.f;
#pragma unroll
        for (int x = 0; x < 16; x++) t += red[tid * 17 + x];
        g_attp[(b * Pp + tid) * 4 + ktile] = t;
    }
}

// ---------------------------------------------------------------------------
// Kernel 5: softmax + attention-weighted encoding
// ---------------------------------------------------------------------------
__global__ void __launch_bounds__(256)
k_softmax_awe(const float* __restrict__ enc, const float* __restrict__ bf,
              float* __restrict__ out) {
    __shared__ float al[Pp];
    __shared__ float inv_s;
    const int b = blockIdx.x;
    const int tid = threadIdx.x;

    if (tid < Pp) {
        const float* ap = g_attp + (size_t)(b * Pp + tid) * 4;
        al[tid] = ap[0] + ap[1] + ap[2] + ap[3] + bf[0];
    }
    __syncthreads();
    if (tid == 0) {
        float m = al[0];
        for (int p = 1; p < Pp; p++) m = fmaxf(m, al[p]);
        float ssum = 0.f;
        for (int p = 0; p < Pp; p++) { al[p] = expf(al[p] - m); ssum += al[p]; }
        inv_s = 1.f / ssum;
    }
    __syncthreads();
    if (tid < Pp) {
        al[tid] *= inv_s;
        out[(size_t)Bb * Ee + b * Pp + tid] = al[tid];
    }
    __syncthreads();

    const float* encb = enc + (size_t)b * Pp * Ee;
#pragma unroll
    for (int r = 0; r < Ee / 256; r++) {
        const int e = r * 256 + tid;
        float a0 = 0.f, a1 = 0.f, a2 = 0.f, a3 = 0.f;
        for (int p = 0; p < 48; p += 4) {
            a0 += encb[(size_t)(p + 0) * Ee + e] * al[p + 0];
            a1 += encb[(size_t)(p + 1) * Ee + e] * al[p + 1];
            a2 += encb[(size_t)(p + 2) * Ee + e] * al[p + 2];
            a3 += encb[(size_t)(p + 3) * Ee + e] * al[p + 3];
        }
        a0 += encb[(size_t)48 * Ee + e] * al[48];
        out[(size_t)b * Ee + e] = a0 + a1 + a2 + a3;
    }
}

// ---------------------------------------------------------------------------
// Launch
// ---------------------------------------------------------------------------
extern "C" void kernel_launch(void* const* d_in, const int* in_sizes, int n_in,
                              void* d_out, int out_size) {
    const float* enc = (const float*)d_in[0];  // [128,49,2048]
    const float* dh  = (const float*)d_in[1];  // [128,512]
    const float* We  = (const float*)d_in[2];  // [512,2048]
    const float* be  = (const float*)d_in[3];  // [512]
    const float* Wd  = (const float*)d_in[4];  // [512,512]
    const float* bd  = (const float*)d_in[5];  // [512]
    const float* Wb  = (const float*)d_in[6];  // [512,512,512]
    const float* bb  = (const float*)d_in[7];  // [512]
    const float* Wf  = (const float*)d_in[8];  // [1,512]
    const float* bf  = (const float*)d_in[9];  // [1]
    float* out = (float*)d_out;

    cudaFuncSetAttribute((const void*)&hmma_gemm<6272, 512, 2048, 0, 0>,
                         cudaFuncAttributeMaxDynamicSharedMemorySize, DSMEM);
    cudaFuncSetAttribute((const void*)&hmma_gemm<128, 262144, 512, 1, 1>,
                         cudaFuncAttributeMaxDynamicSharedMemorySize, DSMEM);
    cudaFuncSetAttribute((const void*)&k_bil_att,
                         cudaFuncAttributeMaxDynamicSharedMemorySize, BIL_SMEM);

    // att2 = dh @ Wd^T + bd
    k_att2<<<128, 256>>>(dh, Wd, bd);

    // att1 = enc @ We^T + be  -> split-bf16 planes (M=6272, N=512, K=2048)
    hmma_gemm<6272, 512, 2048, 0, 0>
        <<<dim3(512 / 128, 6272 / 128), 256, DSMEM>>>(enc, We, be);

    // u = att2 @ Wb_flat^T -> split-bf16 planes (M=128, N=262144, K=512)
    hmma_gemm<128, 262144, 512, 1, 1>
        <<<dim3(262144 / 128, 1), 256, DSMEM>>>(nullptr, Wb, nullptr);

    // bil + relu*Wf partial-att (fused, HMMA on split planes)
    k_bil_att<<<dim3(4, 128), 256, BIL_SMEM>>>(bb, Wf);

    // softmax + attention-weighted encoding
    k_softmax_awe<<<128, 256>>>(enc, bf, out);
}